// round 2
// baseline (speedup 1.0000x reference)
#include <cuda_runtime.h>
#include <cstdint>

#define BATCH 8
#define HH    64
#define WW_   64
#define TT    4096
#define CC    256
#define DD    512
#define MM    (BATCH * TT)   // 32768

// ---------------- scratch (static device globals; no runtime alloc) ----------
__device__ float g_comb[25 * CC];                       // combined 5x5 depthwise weights, [25][C]
__device__ float g_xf[BATCH * TT * CC];                 // 32MB
__device__ float g_k [BATCH * TT * CC];                 // 32MB
__device__ float g_v [BATCH * TT * CC];                 // 32MB
__device__ float g_sr[BATCH * TT * CC];                 // 32MB (sigmoid(r))
__device__ float g_xs[BATCH * TT * DD];                 // 64MB (wkv out * srs)

// ---------------- 1) combine identity + 1x1 + 3x3 + 5x5 into one 5x5 ---------
__global__ void combine_weights_kernel(const float* __restrict__ alpha,
                                       const float* __restrict__ cw1,
                                       const float* __restrict__ cw3,
                                       const float* __restrict__ cw5)
{
    int c = threadIdx.x;  // 256 threads, 1 block
    float a0 = alpha[0], a1 = alpha[1], a2 = alpha[2], a3 = alpha[3];
    #pragma unroll
    for (int j = 0; j < 5; j++) {
        #pragma unroll
        for (int i = 0; i < 5; i++) {
            float v = a3 * cw5[c * 25 + j * 5 + i];
            if (j >= 1 && j <= 3 && i >= 1 && i <= 3)
                v += a2 * cw3[c * 9 + (j - 1) * 3 + (i - 1)];
            if (j == 2 && i == 2)
                v += a1 * cw1[c] + a0;
            g_comb[(j * 5 + i) * CC + c] = v;
        }
    }
}

// ---------------- 2) depthwise 5x5 conv, channels-last, sliding window -------
// block: 256 threads = all channels for one (b, xcol); loops over y with a
// 5x5 register window (5 loads/output instead of 25).
__global__ __launch_bounds__(256) void omni_conv_kernel(const float* __restrict__ x)
{
    int b  = blockIdx.x >> 6;
    int xc = blockIdx.x & 63;
    int c  = threadIdx.x;

    float wgt[25];
    #pragma unroll
    for (int j = 0; j < 25; j++) wgt[j] = g_comb[j * CC + c];

    const float* xin  = x    + (size_t)b * TT * CC + c;
    float*       xout = g_xf + (size_t)b * TT * CC + (size_t)xc * CC + c;

    float win[5][5];
    #pragma unroll
    for (int i = 0; i < 5; i++) { win[0][i] = 0.f; win[1][i] = 0.f; }
    #pragma unroll
    for (int r = 0; r < 3; r++) {
        #pragma unroll
        for (int i = 0; i < 5; i++) {
            int xx = xc - 2 + i;
            win[2 + r][i] = (xx >= 0 && xx < WW_) ? xin[((size_t)r * WW_ + xx) * CC] : 0.f;
        }
    }

    #pragma unroll 2
    for (int y = 0; y < HH; y++) {
        float acc = 0.f;
        #pragma unroll
        for (int j = 0; j < 5; j++)
            #pragma unroll
            for (int i = 0; i < 5; i++)
                acc = fmaf(wgt[j * 5 + i], win[j][i], acc);
        xout[(size_t)y * WW_ * CC] = acc;

        // shift window, load row y+3
        #pragma unroll
        for (int j = 0; j < 4; j++)
            #pragma unroll
            for (int i = 0; i < 5; i++) win[j][i] = win[j + 1][i];
        int row = y + 3;
        #pragma unroll
        for (int i = 0; i < 5; i++) {
            int xx = xc - 2 + i;
            win[4][i] = (row < HH && xx >= 0 && xx < WW_)
                        ? xin[((size_t)row * WW_ + xx) * CC] : 0.f;
        }
    }
}

// ---------------- 3) fp32 SGEMM: Out[M,256] = A[M,K] * W[256,K]^T ------------
// 128x128x16 tile, 256 threads, 8x8 register tile per thread.
// act=1 applies sigmoid in the epilogue.
__global__ __launch_bounds__(256) void gemm_kernel(const float* __restrict__ A,
                                                   const float* __restrict__ W,
                                                   float* __restrict__ Out,
                                                   int K, int act)
{
    __shared__ float As[16][128];
    __shared__ float Ws[16][128];

    const int tid = threadIdx.x;
    const int bn  = blockIdx.x * 128;
    const size_t bm = (size_t)blockIdx.y * 128;
    const int tx = tid & 15, ty = tid >> 4;
    const int lr = tid >> 2;           // 0..63
    const int lc = (tid & 3) << 2;     // 0,4,8,12

    const float* Ap = A + (bm + lr) * (size_t)K + lc;
    const float* Wp = W + (size_t)(bn + lr) * K + lc;

    float acc[8][8];
    #pragma unroll
    for (int i = 0; i < 8; i++)
        #pragma unroll
        for (int j = 0; j < 8; j++) acc[i][j] = 0.f;

    for (int k0 = 0; k0 < K; k0 += 16) {
        float4 a0 = *(const float4*)Ap;
        float4 a1 = *(const float4*)(Ap + (size_t)64 * K);
        float4 w0 = *(const float4*)Wp;
        float4 w1 = *(const float4*)(Wp + (size_t)64 * K);
        Ap += 16; Wp += 16;

        __syncthreads();
        As[lc + 0][lr] = a0.x; As[lc + 1][lr] = a0.y;
        As[lc + 2][lr] = a0.z; As[lc + 3][lr] = a0.w;
        As[lc + 0][lr + 64] = a1.x; As[lc + 1][lr + 64] = a1.y;
        As[lc + 2][lr + 64] = a1.z; As[lc + 3][lr + 64] = a1.w;
        Ws[lc + 0][lr] = w0.x; Ws[lc + 1][lr] = w0.y;
        Ws[lc + 2][lr] = w0.z; Ws[lc + 3][lr] = w0.w;
        Ws[lc + 0][lr + 64] = w1.x; Ws[lc + 1][lr + 64] = w1.y;
        Ws[lc + 2][lr + 64] = w1.z; Ws[lc + 3][lr + 64] = w1.w;
        __syncthreads();

        #pragma unroll
        for (int kk = 0; kk < 16; kk++) {
            float ar[8], wr[8];
            *(float4*)&ar[0] = *(const float4*)&As[kk][ty * 8];
            *(float4*)&ar[4] = *(const float4*)&As[kk][ty * 8 + 4];
            *(float4*)&wr[0] = *(const float4*)&Ws[kk][tx * 8];
            *(float4*)&wr[4] = *(const float4*)&Ws[kk][tx * 8 + 4];
            #pragma unroll
            for (int i = 0; i < 8; i++)
                #pragma unroll
                for (int j = 0; j < 8; j++)
                    acc[i][j] = fmaf(ar[i], wr[j], acc[i][j]);
        }
    }

    #pragma unroll
    for (int i = 0; i < 8; i++) {
        size_t row = bm + (size_t)ty * 8 + i;
        float* op = Out + row * 256 + bn + tx * 8;
        #pragma unroll
        for (int j = 0; j < 8; j++) {
            float v = acc[i][j];
            if (act) v = 1.0f / (1.0f + __expf(-v));
            op[j] = v;
        }
    }
}

// ---------------- 4) WKV scan: one thread per (b, d) chain -------------------
// d<256 reads k/v in H-major order; d>=256 reads the W-major reorder directly
// (k1[b, y*64+x] = k[b, x*64+y]) -- nothing materialized. Output fused with sr.
__global__ __launch_bounds__(32) void wkv_kernel(const float* __restrict__ sd,
                                                 const float* __restrict__ sf)
{
    int gid = blockIdx.x * 32 + threadIdx.x;   // 0..4095
    int b = gid >> 9;
    int d = gid & 511;
    int c = d & 255;
    bool second = d >= 256;

    float wdec = -__expf(sd[d] * (1.0f / (float)TT));
    float u    =  sf[d] * (1.0f / (float)TT);

    const size_t base = (size_t)b * TT * CC + c;
    float* xsp = g_xs + (size_t)b * TT * DD + d;

    float a = 0.f, bb = 0.f, pp = -1e38f;

    for (int t0 = 0; t0 < TT; t0 += 8) {
        float kb[8], vb[8], sb[8];
        #pragma unroll
        for (int i = 0; i < 8; i++) {
            int t  = t0 + i;
            int ti = second ? (((t & 63) << 6) | (t >> 6)) : t;
            size_t off = base + (size_t)ti * CC;
            kb[i] = g_k[off];
            vb[i] = g_v[off];
            sb[i] = g_sr[base + (size_t)t * CC];
        }
        #pragma unroll
        for (int i = 0; i < 8; i++) {
            float kt = kb[i], vt = vb[i];
            float ww = u + kt;
            float p  = fmaxf(pp, ww);
            float e1 = __expf(pp - p);
            float e2 = __expf(ww - p);
            float out = __fdividef(e1 * a + e2 * vt, e1 * bb + e2);
            float ww2 = pp + wdec;
            float p2  = fmaxf(ww2, kt);
            float f1  = __expf(ww2 - p2);
            float f2  = __expf(kt - p2);
            a  = f1 * a  + f2 * vt;
            bb = f1 * bb + f2;
            pp = p2;
            xsp[(size_t)(t0 + i) * DD] = out * sb[i];
        }
    }
}

// ---------------- launch -----------------------------------------------------
extern "C" void kernel_launch(void* const* d_in, const int* in_sizes, int n_in,
                              void* d_out, int out_size)
{
    const float* x     = (const float*)d_in[0];
    const float* alpha = (const float*)d_in[1];
    const float* cw1   = (const float*)d_in[2];
    const float* cw3   = (const float*)d_in[3];
    const float* cw5   = (const float*)d_in[4];
    const float* Wk    = (const float*)d_in[5];
    const float* Wv    = (const float*)d_in[6];
    const float* Wr    = (const float*)d_in[7];
    const float* Wo    = (const float*)d_in[8];
    const float* sd    = (const float*)d_in[9];
    const float* sf    = (const float*)d_in[10];

    float *xf, *k, *v, *sr, *xs;
    cudaGetSymbolAddress((void**)&xf, g_xf);
    cudaGetSymbolAddress((void**)&k,  g_k);
    cudaGetSymbolAddress((void**)&v,  g_v);
    cudaGetSymbolAddress((void**)&sr, g_sr);
    cudaGetSymbolAddress((void**)&xs, g_xs);

    combine_weights_kernel<<<1, 256>>>(alpha, cw1, cw3, cw5);
    omni_conv_kernel<<<BATCH * WW_, 256>>>(x);

    dim3 ggrid(2, MM / 128);   // N=256 / 128, M=32768 / 128
    gemm_kernel<<<ggrid, 256>>>(xf, Wk, k, CC, 0);
    gemm_kernel<<<ggrid, 256>>>(xf, Wv, v, CC, 0);
    gemm_kernel<<<ggrid, 256>>>(xf, Wr, sr, CC, 1);

    wkv_kernel<<<128, 32>>>(sd, sf);

    gemm_kernel<<<ggrid, 256>>>(xs, Wo, (float*)d_out, DD, 0);
}

// round 3
// speedup vs baseline: 1.5625x; 1.5625x over previous
#include <cuda_runtime.h>
#include <cstdint>

#define BATCH 8
#define HH    64
#define WW_   64
#define TT    4096
#define CC    256
#define DD    512
#define MM    (BATCH * TT)   // 32768

// ---------------- scratch (static device globals; no runtime alloc) ----------
__device__ float g_comb[25 * CC];
__device__ float g_xf[BATCH * TT * CC];                 // 32MB
__device__ float g_k [BATCH * TT * CC];                 // 32MB
__device__ float g_v [BATCH * TT * CC];                 // 32MB
__device__ float g_sr[BATCH * TT * CC];                 // 32MB
__device__ float g_xs[BATCH * TT * DD];                 // 64MB

// ---------------- 1) combine identity + 1x1 + 3x3 + 5x5 into one 5x5 ---------
__global__ void combine_weights_kernel(const float* __restrict__ alpha,
                                       const float* __restrict__ cw1,
                                       const float* __restrict__ cw3,
                                       const float* __restrict__ cw5)
{
    int c = threadIdx.x;
    float a0 = alpha[0], a1 = alpha[1], a2 = alpha[2], a3 = alpha[3];
    #pragma unroll
    for (int j = 0; j < 5; j++) {
        #pragma unroll
        for (int i = 0; i < 5; i++) {
            float v = a3 * cw5[c * 25 + j * 5 + i];
            if (j >= 1 && j <= 3 && i >= 1 && i <= 3)
                v += a2 * cw3[c * 9 + (j - 1) * 3 + (i - 1)];
            if (j == 2 && i == 2)
                v += a1 * cw1[c] + a0;
            g_comb[(j * 5 + i) * CC + c] = v;
        }
    }
}

// ---------------- 2) depthwise 5x5 conv, channels-last, sliding window -------
__global__ __launch_bounds__(256) void omni_conv_kernel(const float* __restrict__ x)
{
    int b  = blockIdx.x >> 6;
    int xc = blockIdx.x & 63;
    int c  = threadIdx.x;

    float wgt[25];
    #pragma unroll
    for (int j = 0; j < 25; j++) wgt[j] = g_comb[j * CC + c];

    const float* xin  = x    + (size_t)b * TT * CC + c;
    float*       xout = g_xf + (size_t)b * TT * CC + (size_t)xc * CC + c;

    float win[5][5];
    #pragma unroll
    for (int i = 0; i < 5; i++) { win[0][i] = 0.f; win[1][i] = 0.f; }
    #pragma unroll
    for (int r = 0; r < 3; r++) {
        #pragma unroll
        for (int i = 0; i < 5; i++) {
            int xx = xc - 2 + i;
            win[2 + r][i] = (xx >= 0 && xx < WW_) ? xin[((size_t)r * WW_ + xx) * CC] : 0.f;
        }
    }

    #pragma unroll 2
    for (int y = 0; y < HH; y++) {
        float acc = 0.f;
        #pragma unroll
        for (int j = 0; j < 5; j++)
            #pragma unroll
            for (int i = 0; i < 5; i++)
                acc = fmaf(wgt[j * 5 + i], win[j][i], acc);
        xout[(size_t)y * WW_ * CC] = acc;

        #pragma unroll
        for (int j = 0; j < 4; j++)
            #pragma unroll
            for (int i = 0; i < 5; i++) win[j][i] = win[j + 1][i];
        int row = y + 3;
        #pragma unroll
        for (int i = 0; i < 5; i++) {
            int xx = xc - 2 + i;
            win[4][i] = (row < HH && xx >= 0 && xx < WW_)
                        ? xin[((size_t)row * WW_ + xx) * CC] : 0.f;
        }
    }
}

// ---------------- 3) tf32 tensor-core GEMM: Out[M,256] = A[M,K] * W[N,K]^T ---
// 128x128x32 block tile, 8 warps (2x4), warp tile 64x32, mma.sync m16n8k8.
// smem inner stride 36: fragment-load bank = (4*row + col) % 32, conflict-free.
__device__ __forceinline__ unsigned f2tf32(float f) {
    unsigned u;
    asm("cvt.rna.tf32.f32 %0, %1;" : "=r"(u) : "f"(f));
    return u;
}

__global__ __launch_bounds__(256) void gemm_tf32_kernel(const float* __restrict__ A,
                                                        const float* __restrict__ W,
                                                        float* __restrict__ Out,
                                                        int K, int act)
{
    __shared__ unsigned As[128][36];
    __shared__ unsigned Ws[128][36];

    const int tid  = threadIdx.x;
    const int bn   = blockIdx.x * 128;
    const size_t bm = (size_t)blockIdx.y * 128;
    const int lane = tid & 31, wid = tid >> 5;
    const int wm = (wid & 1) * 64;
    const int wn = (wid >> 1) * 32;
    const int qr = lane >> 2;   // 0..7
    const int qc = lane & 3;    // 0..3

    const int lrow = tid >> 1;          // 0..127
    const int lcol = (tid & 1) * 16;    // 0 / 16

    const float* Ap = A + (bm + lrow) * (size_t)K + lcol;
    const float* Wp = W + (size_t)(bn + lrow) * K + lcol;

    float acc[4][4][4];
    #pragma unroll
    for (int mf = 0; mf < 4; mf++)
        #pragma unroll
        for (int nf = 0; nf < 4; nf++)
            #pragma unroll
            for (int i = 0; i < 4; i++) acc[mf][nf][i] = 0.f;

    float4 pa[4], pw[4];
    #pragma unroll
    for (int i = 0; i < 4; i++) {
        pa[i] = *(const float4*)(Ap + i * 4);
        pw[i] = *(const float4*)(Wp + i * 4);
    }

    for (int k0 = 0; k0 < K; k0 += 32) {
        __syncthreads();
        #pragma unroll
        for (int i = 0; i < 4; i++) {
            uint4 sa, sw;
            sa.x = f2tf32(pa[i].x); sa.y = f2tf32(pa[i].y);
            sa.z = f2tf32(pa[i].z); sa.w = f2tf32(pa[i].w);
            sw.x = f2tf32(pw[i].x); sw.y = f2tf32(pw[i].y);
            sw.z = f2tf32(pw[i].z); sw.w = f2tf32(pw[i].w);
            *(uint4*)&As[lrow][lcol + i * 4] = sa;
            *(uint4*)&Ws[lrow][lcol + i * 4] = sw;
        }
        __syncthreads();

        if (k0 + 32 < K) {
            Ap += 32; Wp += 32;
            #pragma unroll
            for (int i = 0; i < 4; i++) {
                pa[i] = *(const float4*)(Ap + i * 4);
                pw[i] = *(const float4*)(Wp + i * 4);
            }
        }

        #pragma unroll
        for (int k8 = 0; k8 < 4; k8++) {
            const int kc = k8 * 8;
            unsigned b0[4], b1[4];
            #pragma unroll
            for (int nf = 0; nf < 4; nf++) {
                int n = wn + nf * 8 + qr;
                b0[nf] = Ws[n][kc + qc];
                b1[nf] = Ws[n][kc + qc + 4];
            }
            #pragma unroll
            for (int mf = 0; mf < 4; mf++) {
                int r0 = wm + mf * 16 + qr;
                unsigned a0 = As[r0][kc + qc];
                unsigned a1 = As[r0 + 8][kc + qc];
                unsigned a2 = As[r0][kc + qc + 4];
                unsigned a3 = As[r0 + 8][kc + qc + 4];
                #pragma unroll
                for (int nf = 0; nf < 4; nf++) {
                    asm volatile(
                        "mma.sync.aligned.m16n8k8.row.col.f32.tf32.tf32.f32 "
                        "{%0,%1,%2,%3}, {%4,%5,%6,%7}, {%8,%9}, {%0,%1,%2,%3};"
                        : "+f"(acc[mf][nf][0]), "+f"(acc[mf][nf][1]),
                          "+f"(acc[mf][nf][2]), "+f"(acc[mf][nf][3])
                        : "r"(a0), "r"(a1), "r"(a2), "r"(a3),
                          "r"(b0[nf]), "r"(b1[nf]));
                }
            }
        }
    }

    #pragma unroll
    for (int mf = 0; mf < 4; mf++) {
        size_t r0 = bm + wm + mf * 16 + qr;
        #pragma unroll
        for (int nf = 0; nf < 4; nf++) {
            int col = bn + wn + nf * 8 + qc * 2;
            float c0 = acc[mf][nf][0], c1 = acc[mf][nf][1];
            float c2 = acc[mf][nf][2], c3 = acc[mf][nf][3];
            if (act) {
                c0 = 1.0f / (1.0f + __expf(-c0));
                c1 = 1.0f / (1.0f + __expf(-c1));
                c2 = 1.0f / (1.0f + __expf(-c2));
                c3 = 1.0f / (1.0f + __expf(-c3));
            }
            *(float2*)(Out + r0 * 256 + col)       = make_float2(c0, c1);
            *(float2*)(Out + (r0 + 8) * 256 + col) = make_float2(c2, c3);
        }
    }
}

// ---------------- 4) WKV scan: one thread per (b, d) chain -------------------
// MUFU-reduced: in each stabilized exp pair, the max branch is exp(0)=1, so
// only ONE exp per pair is needed (2 exps + 1 rcp per step instead of 4 + 1).
__global__ __launch_bounds__(32) void wkv_kernel(const float* __restrict__ sd,
                                                 const float* __restrict__ sf)
{
    int gid = blockIdx.x * 32 + threadIdx.x;   // 0..4095
    int b = gid >> 9;
    int d = gid & 511;
    int c = d & 255;
    bool second = d >= 256;

    float wdec = -__expf(sd[d] * (1.0f / (float)TT));
    float u    =  sf[d] * (1.0f / (float)TT);

    const size_t base = (size_t)b * TT * CC + c;
    float* xsp = g_xs + (size_t)b * TT * DD + d;

    float a = 0.f, bb = 0.f, pp = -1e38f;

    for (int t0 = 0; t0 < TT; t0 += 8) {
        float kb[8], vb[8], sb[8];
        #pragma unroll
        for (int i = 0; i < 8; i++) {
            int t  = t0 + i;
            int ti = second ? (((t & 63) << 6) | (t >> 6)) : t;
            size_t off = base + (size_t)ti * CC;
            kb[i] = g_k[off];
            vb[i] = g_v[off];
            sb[i] = g_sr[base + (size_t)t * CC];
        }
        #pragma unroll
        for (int i = 0; i < 8; i++) {
            float kt = kb[i], vt = vb[i];
            float ww = u + kt;
            float d1 = pp - ww;                 // exp(min-max) only; other is 1
            float e  = __expf(-fabsf(d1));
            float e1 = (d1 >= 0.f) ? 1.f : e;
            float e2 = (d1 >= 0.f) ? e : 1.f;
            float out = __fdividef(e1 * a + e2 * vt, e1 * bb + e2);

            float ww2 = pp + wdec;
            float d2 = ww2 - kt;
            float f  = __expf(-fabsf(d2));
            float f1 = (d2 >= 0.f) ? 1.f : f;
            float f2 = (d2 >= 0.f) ? f : 1.f;
            a  = f1 * a  + f2 * vt;
            bb = f1 * bb + f2;
            pp = fmaxf(ww2, kt);
            xsp[(size_t)(t0 + i) * DD] = out * sb[i];
        }
    }
}

// ---------------- launch -----------------------------------------------------
extern "C" void kernel_launch(void* const* d_in, const int* in_sizes, int n_in,
                              void* d_out, int out_size)
{
    const float* x     = (const float*)d_in[0];
    const float* alpha = (const float*)d_in[1];
    const float* cw1   = (const float*)d_in[2];
    const float* cw3   = (const float*)d_in[3];
    const float* cw5   = (const float*)d_in[4];
    const float* Wk    = (const float*)d_in[5];
    const float* Wv    = (const float*)d_in[6];
    const float* Wr    = (const float*)d_in[7];
    const float* Wo    = (const float*)d_in[8];
    const float* sd    = (const float*)d_in[9];
    const float* sf    = (const float*)d_in[10];

    float *xf, *k, *v, *sr, *xs;
    cudaGetSymbolAddress((void**)&xf, g_xf);
    cudaGetSymbolAddress((void**)&k,  g_k);
    cudaGetSymbolAddress((void**)&v,  g_v);
    cudaGetSymbolAddress((void**)&sr, g_sr);
    cudaGetSymbolAddress((void**)&xs, g_xs);

    combine_weights_kernel<<<1, 256>>>(alpha, cw1, cw3, cw5);
    omni_conv_kernel<<<BATCH * WW_, 256>>>(x);

    dim3 ggrid(2, MM / 128);
    gemm_tf32_kernel<<<ggrid, 256>>>(xf, Wk, k, CC, 0);
    gemm_tf32_kernel<<<ggrid, 256>>>(xf, Wv, v, CC, 0);
    gemm_tf32_kernel<<<ggrid, 256>>>(xf, Wr, sr, CC, 1);

    wkv_kernel<<<128, 32>>>(sd, sf);

    gemm_tf32_kernel<<<ggrid, 256>>>(xs, Wo, (float*)d_out, DD, 0);
}

// round 7
// speedup vs baseline: 3.3256x; 2.1285x over previous
#include <cuda_runtime.h>
#include <cstdint>

#define BATCH 8
#define HH    64
#define WW_   64
#define TT    4096
#define CC    256
#define DD    512
#define MM    (BATCH * TT)   // 32768

#define NCHAIN 4096          // B * D
#define NCHUNK 32
#define CHLEN  128           // TT / NCHUNK

// ---------------- scratch (static device globals; no runtime alloc) ----------
__device__ float g_comb[25 * CC];
__device__ float g_xf[BATCH * TT * CC];                 // 32MB
__device__ float g_k [BATCH * TT * CC];                 // 32MB
__device__ float g_v [BATCH * TT * CC];                 // 32MB
__device__ float g_sr[BATCH * TT * CC];                 // 32MB
__device__ float g_xs[BATCH * TT * DD];                 // 64MB
// chunk states [chunk][chain] and exclusive-prefix states
__device__ float g_sa[NCHUNK * NCHAIN];
__device__ float g_sb[NCHUNK * NCHAIN];
__device__ float g_sp[NCHUNK * NCHAIN];
__device__ float g_pa[NCHUNK * NCHAIN];
__device__ float g_pb[NCHUNK * NCHAIN];
__device__ float g_pp[NCHUNK * NCHAIN];

// ---------------- 1) combine identity + 1x1 + 3x3 + 5x5 into one 5x5 ---------
__global__ void combine_weights_kernel(const float* __restrict__ alpha,
                                       const float* __restrict__ cw1,
                                       const float* __restrict__ cw3,
                                       const float* __restrict__ cw5)
{
    int c = threadIdx.x;
    float a0 = alpha[0], a1 = alpha[1], a2 = alpha[2], a3 = alpha[3];
    #pragma unroll
    for (int j = 0; j < 5; j++) {
        #pragma unroll
        for (int i = 0; i < 5; i++) {
            float v = a3 * cw5[c * 25 + j * 5 + i];
            if (j >= 1 && j <= 3 && i >= 1 && i <= 3)
                v += a2 * cw3[c * 9 + (j - 1) * 3 + (i - 1)];
            if (j == 2 && i == 2)
                v += a1 * cw1[c] + a0;
            g_comb[(j * 5 + i) * CC + c] = v;
        }
    }
}

// ---------------- 2) depthwise 5x5 conv, channels-last, sliding window -------
__global__ __launch_bounds__(256) void omni_conv_kernel(const float* __restrict__ x)
{
    int b  = blockIdx.x >> 6;
    int xc = blockIdx.x & 63;
    int c  = threadIdx.x;

    float wgt[25];
    #pragma unroll
    for (int j = 0; j < 25; j++) wgt[j] = g_comb[j * CC + c];

    const float* xin  = x    + (size_t)b * TT * CC + c;
    float*       xout = g_xf + (size_t)b * TT * CC + (size_t)xc * CC + c;

    float win[5][5];
    #pragma unroll
    for (int i = 0; i < 5; i++) { win[0][i] = 0.f; win[1][i] = 0.f; }
    #pragma unroll
    for (int r = 0; r < 3; r++) {
        #pragma unroll
        for (int i = 0; i < 5; i++) {
            int xx = xc - 2 + i;
            win[2 + r][i] = (xx >= 0 && xx < WW_) ? xin[((size_t)r * WW_ + xx) * CC] : 0.f;
        }
    }

    #pragma unroll 2
    for (int y = 0; y < HH; y++) {
        float acc = 0.f;
        #pragma unroll
        for (int j = 0; j < 5; j++)
            #pragma unroll
            for (int i = 0; i < 5; i++)
                acc = fmaf(wgt[j * 5 + i], win[j][i], acc);
        xout[(size_t)y * WW_ * CC] = acc;

        #pragma unroll
        for (int j = 0; j < 4; j++)
            #pragma unroll
            for (int i = 0; i < 5; i++) win[j][i] = win[j + 1][i];
        int row = y + 3;
        #pragma unroll
        for (int i = 0; i < 5; i++) {
            int xx = xc - 2 + i;
            win[4][i] = (row < HH && xx >= 0 && xx < WW_)
                        ? xin[((size_t)row * WW_ + xx) * CC] : 0.f;
        }
    }
}

// ---------------- 3) tf32 tensor-core GEMM (double-buffered smem) ------------
__device__ __forceinline__ unsigned f2tf32(float f) {
    unsigned u;
    asm("cvt.rna.tf32.f32 %0, %1;" : "=r"(u) : "f"(f));
    return u;
}

__global__ __launch_bounds__(256) void gemm_tf32_kernel(const float* __restrict__ A,
                                                        const float* __restrict__ W,
                                                        float* __restrict__ Out,
                                                        int K, int act)
{
    __shared__ unsigned As[2][128][36];
    __shared__ unsigned Ws[2][128][36];

    const int tid  = threadIdx.x;
    const int bn   = blockIdx.x * 128;
    const size_t bm = (size_t)blockIdx.y * 128;
    const int lane = tid & 31, wid = tid >> 5;
    const int wm = (wid & 1) * 64;
    const int wn = (wid >> 1) * 32;
    const int qr = lane >> 2;
    const int qc = lane & 3;

    const int lrow = tid >> 1;
    const int lcol = (tid & 1) * 16;

    const float* Ap = A + (bm + lrow) * (size_t)K + lcol;
    const float* Wp = W + (size_t)(bn + lrow) * K + lcol;

    float acc[4][4][4];
    #pragma unroll
    for (int mf = 0; mf < 4; mf++)
        #pragma unroll
        for (int nf = 0; nf < 4; nf++)
            #pragma unroll
            for (int i = 0; i < 4; i++) acc[mf][nf][i] = 0.f;

    float4 pa[4], pw[4];
    #pragma unroll
    for (int i = 0; i < 4; i++) {
        pa[i] = *(const float4*)(Ap + i * 4);
        pw[i] = *(const float4*)(Wp + i * 4);
    }
    // stage tile 0
    #pragma unroll
    for (int i = 0; i < 4; i++) {
        uint4 sa, sw;
        sa.x = f2tf32(pa[i].x); sa.y = f2tf32(pa[i].y);
        sa.z = f2tf32(pa[i].z); sa.w = f2tf32(pa[i].w);
        sw.x = f2tf32(pw[i].x); sw.y = f2tf32(pw[i].y);
        sw.z = f2tf32(pw[i].z); sw.w = f2tf32(pw[i].w);
        *(uint4*)&As[0][lrow][lcol + i * 4] = sa;
        *(uint4*)&Ws[0][lrow][lcol + i * 4] = sw;
    }
    __syncthreads();

    int cur = 0;
    for (int k0 = 0; k0 < K; k0 += 32) {
        const bool more = (k0 + 32 < K);
        if (more) {
            Ap += 32; Wp += 32;
            #pragma unroll
            for (int i = 0; i < 4; i++) {
                pa[i] = *(const float4*)(Ap + i * 4);
                pw[i] = *(const float4*)(Wp + i * 4);
            }
        }

        #pragma unroll
        for (int k8 = 0; k8 < 4; k8++) {
            const int kc = k8 * 8;
            unsigned b0[4], b1[4];
            #pragma unroll
            for (int nf = 0; nf < 4; nf++) {
                int n = wn + nf * 8 + qr;
                b0[nf] = Ws[cur][n][kc + qc];
                b1[nf] = Ws[cur][n][kc + qc + 4];
            }
            #pragma unroll
            for (int mf = 0; mf < 4; mf++) {
                int r0 = wm + mf * 16 + qr;
                unsigned a0 = As[cur][r0][kc + qc];
                unsigned a1 = As[cur][r0 + 8][kc + qc];
                unsigned a2 = As[cur][r0][kc + qc + 4];
                unsigned a3 = As[cur][r0 + 8][kc + qc + 4];
                #pragma unroll
                for (int nf = 0; nf < 4; nf++) {
                    asm volatile(
                        "mma.sync.aligned.m16n8k8.row.col.f32.tf32.tf32.f32 "
                        "{%0,%1,%2,%3}, {%4,%5,%6,%7}, {%8,%9}, {%0,%1,%2,%3};"
                        : "+f"(acc[mf][nf][0]), "+f"(acc[mf][nf][1]),
                          "+f"(acc[mf][nf][2]), "+f"(acc[mf][nf][3])
                        : "r"(a0), "r"(a1), "r"(a2), "r"(a3),
                          "r"(b0[nf]), "r"(b1[nf]));
                }
            }
        }

        if (more) {
            #pragma unroll
            for (int i = 0; i < 4; i++) {
                uint4 sa, sw;
                sa.x = f2tf32(pa[i].x); sa.y = f2tf32(pa[i].y);
                sa.z = f2tf32(pa[i].z); sa.w = f2tf32(pa[i].w);
                sw.x = f2tf32(pw[i].x); sw.y = f2tf32(pw[i].y);
                sw.z = f2tf32(pw[i].z); sw.w = f2tf32(pw[i].w);
                *(uint4*)&As[cur ^ 1][lrow][lcol + i * 4] = sa;
                *(uint4*)&Ws[cur ^ 1][lrow][lcol + i * 4] = sw;
            }
        }
        __syncthreads();
        cur ^= 1;
    }

    #pragma unroll
    for (int mf = 0; mf < 4; mf++) {
        size_t r0 = bm + wm + mf * 16 + qr;
        #pragma unroll
        for (int nf = 0; nf < 4; nf++) {
            int col = bn + wn + nf * 8 + qc * 2;
            float c0 = acc[mf][nf][0], c1 = acc[mf][nf][1];
            float c2 = acc[mf][nf][2], c3 = acc[mf][nf][3];
            if (act) {
                c0 = 1.0f / (1.0f + __expf(-c0));
                c1 = 1.0f / (1.0f + __expf(-c1));
                c2 = 1.0f / (1.0f + __expf(-c2));
                c3 = 1.0f / (1.0f + __expf(-c3));
            }
            *(float2*)(Out + r0 * 256 + col)       = make_float2(c0, c1);
            *(float2*)(Out + (r0 + 8) * 256 + col) = make_float2(c2, c3);
        }
    }
}

// ---------------- 4) WKV chunk-parallel scan ---------------------------------
// state update (no output); one exp per step (max branch is exp(0)=1)
__device__ __forceinline__ void wkv_state(float kt, float vt, float wdec,
                                          float& a, float& b, float& pp)
{
    float ww2 = pp + wdec;
    float d2  = ww2 - kt;
    float f   = __expf(-fabsf(d2));
    float f1  = (d2 >= 0.f) ? 1.f : f;
    float f2  = (d2 >= 0.f) ? f : 1.f;
    a  = f1 * a + f2 * vt;
    b  = f1 * b + f2;
    pp = fmaxf(ww2, kt);
}

// pass1: per-chunk local scan from zero state -> (a,b,p) per [chunk][chain]
__global__ __launch_bounds__(256) void wkv_pass1(const float* __restrict__ sd)
{
    int g     = blockIdx.x * 256 + threadIdx.x;   // 0..131071
    int chain = g & (NCHAIN - 1);
    int chunk = g >> 12;
    int b = chain >> 9;
    int d = chain & 511;
    int c = d & 255;
    bool second = d >= 256;

    float wdec = -__expf(sd[d] * (1.0f / (float)TT));
    const size_t base = (size_t)b * TT * CC + c;

    float a = 0.f, bb = 0.f, pp = -1e38f;
    int tstart = chunk * CHLEN;

    for (int t0 = tstart; t0 < tstart + CHLEN; t0 += 8) {
        float kb[8], vb[8];
        #pragma unroll
        for (int i = 0; i < 8; i++) {
            int t  = t0 + i;
            int ti = second ? (((t & 63) << 6) | (t >> 6)) : t;
            size_t off = base + (size_t)ti * CC;
            kb[i] = g_k[off];
            vb[i] = g_v[off];
        }
        #pragma unroll
        for (int i = 0; i < 8; i++)
            wkv_state(kb[i], vb[i], wdec, a, bb, pp);
    }
    g_sa[chunk * NCHAIN + chain] = a;
    g_sb[chunk * NCHAIN + chain] = bb;
    g_sp[chunk * NCHAIN + chain] = pp;
}

// pass2: exclusive prefix combine across chunks (serial over 32, per chain)
__global__ __launch_bounds__(256) void wkv_pass2(const float* __restrict__ sd)
{
    int chain = blockIdx.x * 256 + threadIdx.x;   // 0..4095
    int d = chain & 511;
    float wdec = -__expf(sd[d] * (1.0f / (float)TT));
    float Lw = (float)CHLEN * wdec;

    float A = 0.f, B = 0.f, P = -1e38f;
    for (int j = 0; j < NCHUNK; j++) {
        g_pa[j * NCHAIN + chain] = A;
        g_pb[j * NCHAIN + chain] = B;
        g_pp[j * NCHAIN + chain] = P;
        float ca = g_sa[j * NCHAIN + chain];
        float cb = g_sb[j * NCHAIN + chain];
        float cp = g_sp[j * NCHAIN + chain];
        float np = P + Lw;
        float p  = fmaxf(np, cp);
        float e1 = __expf(np - p);
        float e2 = __expf(cp - p);
        A = e1 * A + e2 * ca;
        B = e1 * B + e2 * cb;
        P = p;
    }
}

// pass3: re-scan each chunk from its prefix state, producing outputs * sr
__global__ __launch_bounds__(256) void wkv_pass3(const float* __restrict__ sd,
                                                 const float* __restrict__ sf)
{
    int g     = blockIdx.x * 256 + threadIdx.x;
    int chain = g & (NCHAIN - 1);
    int chunk = g >> 12;
    int b = chain >> 9;
    int d = chain & 511;
    int c = d & 255;
    bool second = d >= 256;

    float wdec = -__expf(sd[d] * (1.0f / (float)TT));
    float u    =  sf[d] * (1.0f / (float)TT);

    const size_t base = (size_t)b * TT * CC + c;
    float* xsp = g_xs + (size_t)b * TT * DD + d;

    float a  = g_pa[chunk * NCHAIN + chain];
    float bb = g_pb[chunk * NCHAIN + chain];
    float pp = g_pp[chunk * NCHAIN + chain];

    int tstart = chunk * CHLEN;
    for (int t0 = tstart; t0 < tstart + CHLEN; t0 += 8) {
        float kb[8], vb[8], sb[8];
        #pragma unroll
        for (int i = 0; i < 8; i++) {
            int t  = t0 + i;
            int ti = second ? (((t & 63) << 6) | (t >> 6)) : t;
            size_t off = base + (size_t)ti * CC;
            kb[i] = g_k[off];
            vb[i] = g_v[off];
            sb[i] = g_sr[base + (size_t)t * CC];
        }
        #pragma unroll
        for (int i = 0; i < 8; i++) {
            float kt = kb[i], vt = vb[i];
            float ww = u + kt;
            float d1 = pp - ww;
            float e  = __expf(-fabsf(d1));
            float e1 = (d1 >= 0.f) ? 1.f : e;
            float e2 = (d1 >= 0.f) ? e : 1.f;
            float out = __fdividef(e1 * a + e2 * vt, e1 * bb + e2);
            wkv_state(kt, vt, wdec, a, bb, pp);
            xsp[(size_t)(t0 + i) * DD] = out * sb[i];
        }
    }
}

// ---------------- launch -----------------------------------------------------
extern "C" void kernel_launch(void* const* d_in, const int* in_sizes, int n_in,
                              void* d_out, int out_size)
{
    const float* x     = (const float*)d_in[0];
    const float* alpha = (const float*)d_in[1];
    const float* cw1   = (const float*)d_in[2];
    const float* cw3   = (const float*)d_in[3];
    const float* cw5   = (const float*)d_in[4];
    const float* Wk    = (const float*)d_in[5];
    const float* Wv    = (const float*)d_in[6];
    const float* Wr    = (const float*)d_in[7];
    const float* Wo    = (const float*)d_in[8];
    const float* sd    = (const float*)d_in[9];
    const float* sf    = (const float*)d_in[10];

    float *xf, *k, *v, *sr, *xs;
    cudaGetSymbolAddress((void**)&xf, g_xf);
    cudaGetSymbolAddress((void**)&k,  g_k);
    cudaGetSymbolAddress((void**)&v,  g_v);
    cudaGetSymbolAddress((void**)&sr, g_sr);
    cudaGetSymbolAddress((void**)&xs, g_xs);

    combine_weights_kernel<<<1, 256>>>(alpha, cw1, cw3, cw5);
    omni_conv_kernel<<<BATCH * WW_, 256>>>(x);

    dim3 ggrid(2, MM / 128);
    gemm_tf32_kernel<<<ggrid, 256>>>(xf, Wk, k, CC, 0);
    gemm_tf32_kernel<<<ggrid, 256>>>(xf, Wv, v, CC, 0);
    gemm_tf32_kernel<<<ggrid, 256>>>(xf, Wr, sr, CC, 1);

    wkv_pass1<<<(NCHAIN * NCHUNK) / 256, 256>>>(sd);
    wkv_pass2<<<NCHAIN / 256, 256>>>(sd);
    wkv_pass3<<<(NCHAIN * NCHUNK) / 256, 256>>>(sd, sf);

    gemm_tf32_kernel<<<ggrid, 256>>>(xs, Wo, (float*)d_out, DD, 0);
}